// round 14
// baseline (speedup 1.0000x reference)
#include <cuda_runtime.h>
#include <math_constants.h>

// DynamicRouter: logits = x @ W^T + b + 0.1*noise ; top-2 ; sparse softmax.
// x:[32768,768] f32, W:[8,768], b:[8], noise:[32768,8]
// out: [32768*8] probs, then [32768*2] top-k indices (as f32).
//
// Octet mapping (validated): 8 lanes x 16B = one full 128B line per LDG phase;
// T=4 tokens/octet group amortizes W -> 72 wf/token (L1 ~30%).
// R13 lesson: register-batched MLP failed — 128-reg pin stopped ptxas from
// keeping 12 loads live; DRAM stayed 43%. This round: prefetch.global.L2
// (no destination reg => free depth). Demand loads then hit L2 (~234cyc,
// needs only ~4 in-flight/warp); prefetch stream (distance 4 steps,
// ~16 lines/warp outstanding) keeps DRAM full.

#define ROUTER_D 768
#define ROUTER_E 8
#define TOK_T    4
#define PF_DIST  4

__device__ __forceinline__ void fma_x2(unsigned long long& d,
                                       unsigned long long a,
                                       unsigned long long b) {
    asm("fma.rn.f32x2 %0, %1, %2, %3;" : "=l"(d) : "l"(a), "l"(b), "l"(d));
}
__device__ __forceinline__ float2 unpack2(unsigned long long v) {
    float lo, hi;
    asm("mov.b64 {%0, %1}, %2;" : "=f"(lo), "=f"(hi) : "l"(v));
    return make_float2(lo, hi);
}
__device__ __forceinline__ void prefetch_l2(const void* p) {
    asm volatile("prefetch.global.L2 [%0];" :: "l"(p));
}

__global__ __launch_bounds__(128)
void dynamic_router_kernel(const float* __restrict__ x,
                           const float* __restrict__ W,
                           const float* __restrict__ b,
                           const float* __restrict__ noise,
                           float* __restrict__ out,
                           int n_tokens, long long out_size)
{
    const int tid  = threadIdx.x;
    const int warp = tid >> 5;
    const int lane = tid & 31;
    const int o    = lane & 7;   // 16B slot within a 128B (32-dim) step
    const int g    = lane >> 3;  // octet group 0..3

    // warp covers 16 tokens: token(t) = base + t*4 + g
    const int base = (blockIdx.x * 4 + warp) * (4 * TOK_T);

    // Row bases in 16B units (ulonglong2 = 4 floats)
    const ulonglong2* xr[TOK_T];
    #pragma unroll
    for (int t = 0; t < TOK_T; ++t) {
        int tk = base + t * 4 + g;
        tk = tk < n_tokens ? tk : 0;                   // clamp; stores guarded
        xr[t] = reinterpret_cast<const ulonglong2*>(x + (size_t)tk * ROUTER_D);
    }
    const ulonglong2* wr = reinterpret_cast<const ulonglong2*>(W);

    unsigned long long acc[TOK_T][ROUTER_E];
    #pragma unroll
    for (int t = 0; t < TOK_T; ++t)
        #pragma unroll
        for (int e = 0; e < ROUTER_E; ++e) acc[t][e] = 0ull;

    // Prime the prefetch pipeline: steps 0..PF_DIST-1
    #pragma unroll
    for (int s = 0; s < PF_DIST; ++s)
        #pragma unroll
        for (int t = 0; t < TOK_T; ++t)
            prefetch_l2(&xr[t][s * 8 + o]);

    #pragma unroll 2
    for (int j = 0; j < ROUTER_D / 32; ++j) {          // 24 steps of 32 dims
        // Keep DRAM pipe full: prefetch step j+PF_DIST (fire-and-forget).
        if (j + PF_DIST < ROUTER_D / 32) {
            #pragma unroll
            for (int t = 0; t < TOK_T; ++t)
                prefetch_l2(&xr[t][(j + PF_DIST) * 8 + o]);
        }

        const int idx = j * 8 + o;
        ulonglong2 xv[TOK_T];
        #pragma unroll
        for (int t = 0; t < TOK_T; ++t)
            xv[t] = __ldg(&xr[t][idx]);                // L2 hits (~234cyc)

        #pragma unroll
        for (int e = 0; e < ROUTER_E; ++e) {
            const ulonglong2 wv = __ldg(&wr[e * (ROUTER_D / 4) + idx]); // L1-resident
            #pragma unroll
            for (int t = 0; t < TOK_T; ++t) {
                fma_x2(acc[t][e], xv[t].x, wv.x);
                fma_x2(acc[t][e], xv[t].y, wv.y);
            }
        }
    }

    // Reduce across the 8 lanes of the octet for each (t, e).
    // Lane with o == t keeps token t's logits.
    float lg[ROUTER_E];
    #pragma unroll
    for (int t = 0; t < TOK_T; ++t) {
        #pragma unroll
        for (int e = 0; e < ROUTER_E; ++e) {
            const float2 p = unpack2(acc[t][e]);
            float v = p.x + p.y;
            v += __shfl_xor_sync(0xffffffffu, v, 1);
            v += __shfl_xor_sync(0xffffffffu, v, 2);
            v += __shfl_xor_sync(0xffffffffu, v, 4);
            if (o == t) lg[e] = v;
        }
    }

    const int my_tok = base + o * 4 + g;               // token for epilogue lane
    if (o < TOK_T && my_tok < n_tokens) {
        const float4 n0 = __ldg(reinterpret_cast<const float4*>(noise + (size_t)my_tok * ROUTER_E));
        const float4 n1 = __ldg(reinterpret_cast<const float4*>(noise + (size_t)my_tok * ROUTER_E) + 1);

        lg[0] += __ldg(b + 0) + 0.1f * n0.x;
        lg[1] += __ldg(b + 1) + 0.1f * n0.y;
        lg[2] += __ldg(b + 2) + 0.1f * n0.z;
        lg[3] += __ldg(b + 3) + 0.1f * n0.w;
        lg[4] += __ldg(b + 4) + 0.1f * n1.x;
        lg[5] += __ldg(b + 5) + 0.1f * n1.y;
        lg[6] += __ldg(b + 6) + 0.1f * n1.z;
        lg[7] += __ldg(b + 7) + 0.1f * n1.w;

        // top-1 (strict > keeps lowest index on ties, matching jax.lax.top_k)
        int m1 = 0; float v1 = lg[0];
        #pragma unroll
        for (int e = 1; e < ROUTER_E; ++e)
            if (lg[e] > v1) { v1 = lg[e]; m1 = e; }
        // top-2
        int m2 = -1; float v2 = -CUDART_INF_F;
        #pragma unroll
        for (int e = 0; e < ROUTER_E; ++e)
            if (e != m1 && lg[e] > v2) { v2 = lg[e]; m2 = e; }

        // softmax over {v1, v2}, zeros elsewhere (exp(-inf)=0)
        const float ex  = __expf(v2 - v1);      // <= 1
        const float inv = 1.0f / (1.0f + ex);
        const float p1  = inv;
        const float p2  = ex * inv;

        float pv[ROUTER_E];
        #pragma unroll
        for (int e = 0; e < ROUTER_E; ++e)
            pv[e] = (e == m1) ? p1 : ((e == m2) ? p2 : 0.0f);

        float4* oo = reinterpret_cast<float4*>(out + (size_t)my_tok * ROUTER_E);
        oo[0] = make_float4(pv[0], pv[1], pv[2], pv[3]);
        oo[1] = make_float4(pv[4], pv[5], pv[6], pv[7]);

        // second output: top-k indices (stored as float32 after all probs)
        const long long probs = (long long)n_tokens * ROUTER_E;
        if (out_size >= probs + (long long)n_tokens * 2) {
            float2 iv = make_float2((float)m1, (float)m2);
            *reinterpret_cast<float2*>(out + probs + (size_t)my_tok * 2) = iv;
        }
    }
}

extern "C" void kernel_launch(void* const* d_in, const int* in_sizes, int n_in,
                              void* d_out, int out_size)
{
    const float* x     = (const float*)d_in[0];
    const float* W     = (const float*)d_in[1];
    const float* b     = (const float*)d_in[2];
    const float* noise = (const float*)d_in[3];
    float* out = (float*)d_out;

    const int n_tokens = in_sizes[0] / ROUTER_D;      // 32768
    const int tokens_per_block = 64;                  // 4 warps x 16 tokens
    const int blocks = (n_tokens + tokens_per_block - 1) / tokens_per_block;

    dynamic_router_kernel<<<blocks, 128>>>(x, W, b, noise, out,
                                           n_tokens, (long long)out_size);
}